// round 1
// baseline (speedup 1.0000x reference)
#include <cuda_runtime.h>

#define T_ 2048
#define B_ 256
#define M_ 32

// per-batch nllh scratch (no allocations allowed)
__device__ float g_nllh[B_];

__device__ __forceinline__ float ex2f_(float x) {
    float y; asm("ex2.approx.ftz.f32 %0, %1;" : "=f"(y) : "f"(x)); return y;
}
__device__ __forceinline__ float lg2f_(float x) {
    float y; asm("lg2.approx.ftz.f32 %0, %1;" : "=f"(y) : "f"(x)); return y;
}
__device__ __forceinline__ float rcpf_(float x) {
    float y; asm("rcp.approx.ftz.f32 %0, %1;" : "=f"(y) : "f"(x)); return y;
}

__global__ __launch_bounds__(128, 1)
void crf_scan_kernel(const float* __restrict__ em,     // [T,B,M]
                     const int*   __restrict__ tags,   // [T,B]
                     const float* __restrict__ wt,     // [T,B]
                     const int*   __restrict__ mk,     // [T,B]
                     const float* __restrict__ trans,  // [M,M]
                     const float* __restrict__ startt, // [M]
                     const float* __restrict__ endt)   // [M]
{
    const int warp = threadIdx.x >> 5;
    const int lane = threadIdx.x & 31;
    const int b = blockIdx.x * (blockDim.x >> 5) + warp;
    if (b >= B_) return;

    const float L2E = 1.4426950408889634f;
    const float LN2 = 0.6931471805599453f;
    const unsigned FULL = 0xffffffffu;

    // lane j holds column j of transitions, pre-scaled by log2(e)
    float tc[M_];
#pragma unroll
    for (int i = 0; i < M_; ++i)
        tc[i] = trans[i * M_ + lane] * L2E;

    // alpha0 = start + emissions[0]
    float alpha = startt[lane] + em[(size_t)b * M_ + lane];

    // one-step lookahead prefetch
    float em_cur = em[((size_t)1 * B_ + b) * M_ + lane];
    float w_cur  = wt[0 * B_ + b];
    int   mk_cur = mk[1 * B_ + b];

    for (int t = 1; t < T_; ++t) {
        // prefetch next step (clamped index; value unused on last iter)
        const int tn = (t + 1 < T_) ? (t + 1) : (T_ - 1);
        float em_nxt = em[((size_t)tn * B_ + b) * M_ + lane];
        float w_nxt  = wt[(tn - 1) * B_ + b];
        int   mk_nxt = mk[tn * B_ + b];

        // m = max_i alpha_i
        float m = alpha;
#pragma unroll
        for (int off = 16; off; off >>= 1)
            m = fmaxf(m, __shfl_xor_sync(FULL, m, off));

        float p = ex2f_((alpha - m) * L2E);     // exp(alpha_lane - m)
        float invw = rcpf_(w_cur);

        float s = 0.f;
#pragma unroll
        for (int i = 0; i < M_; ++i)
            s += __shfl_sync(FULL, p, i) * ex2f_(tc[i] * invw);

        float na = em_cur + m + lg2f_(s) * LN2;
        alpha = mk_cur ? na : alpha;

        em_cur = em_nxt; w_cur = w_nxt; mk_cur = mk_nxt;
    }

    // log_Z = logsumexp(alpha + end_transitions)
    {
        float v = alpha + endt[lane];
        float m = v;
#pragma unroll
        for (int off = 16; off; off >>= 1)
            m = fmaxf(m, __shfl_xor_sync(FULL, m, off));
        float e = ex2f_((v - m) * L2E);
#pragma unroll
        for (int off = 16; off; off >>= 1)
            e += __shfl_xor_sync(FULL, e, off);
        alpha = m + lg2f_(e) * LN2;   // reuse alpha as logZ
    }
    const float logZ = alpha;

    // ---- gold-path score: lanes stride over t ----
    float sc = 0.f;
    int cnt = 0;
#pragma unroll 4
    for (int base = 0; base < T_; base += 32) {
        const int t = base + lane;
        const int m_t = mk[t * B_ + b];
        cnt += m_t;
        if (m_t) {
            const int tag = tags[t * B_ + b];   // mask on => masked tag == raw tag
            sc += em[((size_t)t * B_ + b) * M_ + tag];
            if (t > 0) {
                const int mp = mk[(t - 1) * B_ + b];
                const int tagp = mp ? tags[(t - 1) * B_ + b] : 1;
                sc += trans[tagp * M_ + tag] * rcpf_(wt[(t - 1) * B_ + b]);
            }
        }
    }
#pragma unroll
    for (int off = 16; off; off >>= 1) {
        sc  += __shfl_xor_sync(FULL, sc, off);
        cnt += __shfl_xor_sync(FULL, cnt, off);
    }

    if (lane == 0) {
        const int tag0 = tags[0 * B_ + b];              // mask[0] guaranteed on
        const int tlast = tags[(cnt - 1) * B_ + b];     // mask at seq_end is on
        sc += startt[tag0] + endt[tlast];
        g_nllh[b] = logZ - sc;
    }
}

// deterministic fixed-order tree reduction of the 256 per-batch values
__global__ void crf_reduce_kernel(float* __restrict__ out)
{
    __shared__ float sm[B_];
    const int i = threadIdx.x;
    sm[i] = g_nllh[i];
    __syncthreads();
#pragma unroll
    for (int s = B_ / 2; s > 0; s >>= 1) {
        if (i < s) sm[i] += sm[i + s];
        __syncthreads();
    }
    if (i == 0) out[0] = sm[0];
}

extern "C" void kernel_launch(void* const* d_in, const int* in_sizes, int n_in,
                              void* d_out, int out_size)
{
    const float* em     = (const float*)d_in[0];
    const int*   tags   = (const int*)  d_in[1];
    const float* wt     = (const float*)d_in[2];
    const int*   mask   = (const int*)  d_in[3];
    const float* trans  = (const float*)d_in[4];
    const float* startt = (const float*)d_in[5];
    const float* endt   = (const float*)d_in[6];

    crf_scan_kernel<<<B_ / 4, 128>>>(em, tags, wt, mask, trans, startt, endt);
    crf_reduce_kernel<<<1, B_>>>((float*)d_out);
}

// round 2
// speedup vs baseline: 1.6177x; 1.6177x over previous
#include <cuda_runtime.h>

#define T_ 2048
#define B_ 256
#define M_ 32
#define HALF_ 16
#define KPOLY 3
#define PF 4

__device__ float g_nllh[B_];
__device__ int g_done;

__device__ __forceinline__ float ex2f_(float x) {
    float y; asm("ex2.approx.ftz.f32 %0, %1;" : "=f"(y) : "f"(x)); return y;
}
__device__ __forceinline__ float lg2f_(float x) {
    float y; asm("lg2.approx.ftz.f32 %0, %1;" : "=f"(y) : "f"(x)); return y;
}
__device__ __forceinline__ float rcpf_(float x) {
    float y; asm("rcp.approx.ftz.f32 %0, %1;" : "=f"(y) : "f"(x)); return y;
}

// e^x via degree-7 Taylor (|x| <= ~0.9 here; err ~1e-5 abs)
__device__ __forceinline__ float poly_exp(float x) {
    float e = fmaf(x, 1.9841270e-4f, 1.3888889e-3f);
    e = fmaf(x, e, 8.3333333e-3f);
    e = fmaf(x, e, 4.1666668e-2f);
    e = fmaf(x, e, 1.6666667e-1f);
    e = fmaf(x, e, 0.5f);
    e = fmaf(x, e, 1.0f);
    e = fmaf(x, e, 1.0f);
    return e;
}

__global__ __launch_bounds__(128, 1)
void crf_kernel(const float* __restrict__ em,     // [T,B,M]
                const int*   __restrict__ tags,   // [T,B]
                const float* __restrict__ wt,     // [T,B]
                const int*   __restrict__ mk,     // [T,B]
                const float* __restrict__ trans,  // [M,M]
                const float* __restrict__ startt, // [M]
                const float* __restrict__ endt,   // [M]
                float* __restrict__ out)
{
    const int lane = threadIdx.x & 31;
    const int warp = threadIdx.x >> 5;
    const int pair = warp >> 1;   // which batch within CTA
    const int half = warp & 1;    // which half of transition rows
    const int b = blockIdx.x * 2 + pair;
    const int i0 = half * HALF_;
    const unsigned FULL = 0xffffffffu;
    const float L2E = 1.4426950408889634f;
    const float LN2 = 0.6931471805599453f;

    __shared__ float xch[2][2][2][M_];  // [buf][pair][half][lane]
    __shared__ float s_sc[2][2];
    __shared__ int   s_cnt[2][2];
    __shared__ int   s_last;

    // lane j holds trans[i0+k][j]; poly terms keep natural log, mufu terms pre-scaled by log2(e)
    float tc[HALF_];
#pragma unroll
    for (int k = 0; k < HALF_; ++k) {
        float tv = trans[(i0 + k) * M_ + lane];
        tc[k] = (k < KPOLY) ? tv : tv * L2E;
    }

    float alpha = startt[lane] + em[(size_t)b * M_ + lane];

    // exact max of alpha0 (used as shift for steps 1 and 2)
    float m_cur = alpha;
#pragma unroll
    for (int off = 16; off; off >>= 1)
        m_cur = fmaxf(m_cur, __shfl_xor_sync(FULL, m_cur, off));

    // software-pipelined prefetch buffers (depth PF)
    float emb[PF], wb[PF]; int mkb[PF];
#pragma unroll
    for (int j = 0; j < PF; ++j) {
        const int t = 1 + j;
        emb[j] = em[((size_t)t * B_ + b) * M_ + lane];
        wb[j]  = wt[(t - 1) * B_ + b];
        mkb[j] = mk[t * B_ + b];
    }

    int buf = 0;
#pragma unroll 4
    for (int t = 1; t < T_; ++t) {
        const int idx = (t - 1) & (PF - 1);
        const float em_c = emb[idx];
        const float w_c  = wb[idx];
        const int   mk_c = mkb[idx];
        const int tp = t + PF;
        if (tp < T_) {
            emb[idx] = em[((size_t)tp * B_ + b) * M_ + lane];
            wb[idx]  = wt[(tp - 1) * B_ + b];
            mkb[idx] = mk[tp * B_ + b];
        }

        const float m = m_cur;                       // stale-by-1 shift (safe: logsumexp shift-invariant)
        const float p = ex2f_((alpha - m) * L2E);    // exp(alpha_i - m)
        const float invw = rcpf_(w_c);

        // kick off max(alpha_{t-1}) for use at step t+1 — off the critical path
        float mx = alpha;
#pragma unroll
        for (int off = 16; off; off >>= 1)
            mx = fmaxf(mx, __shfl_xor_sync(FULL, mx, off));

        float a0 = 0.f, a1 = 0.f, a2 = 0.f, a3 = 0.f;
#pragma unroll
        for (int k = 0; k < KPOLY; ++k) {            // FMA-pipe exps
            const float e = poly_exp(tc[k] * invw);
            const float pk = __shfl_sync(FULL, p, i0 + k);
            if ((k & 3) == 0)      a0 = fmaf(pk, e, a0);
            else if ((k & 3) == 1) a1 = fmaf(pk, e, a1);
            else if ((k & 3) == 2) a2 = fmaf(pk, e, a2);
            else                   a3 = fmaf(pk, e, a3);
        }
#pragma unroll
        for (int k = KPOLY; k < HALF_; ++k) {        // MUFU exps
            const float e = ex2f_(tc[k] * invw);
            const float pk = __shfl_sync(FULL, p, i0 + k);
            if ((k & 3) == 0)      a0 = fmaf(pk, e, a0);
            else if ((k & 3) == 1) a1 = fmaf(pk, e, a1);
            else if ((k & 3) == 2) a2 = fmaf(pk, e, a2);
            else                   a3 = fmaf(pk, e, a3);
        }
        const float sh = (a0 + a1) + (a2 + a3);

        xch[buf][pair][half][lane] = sh;
        __syncthreads();
        const float s = sh + xch[buf][pair][half ^ 1][lane];
        buf ^= 1;

        const float na = fmaf(lg2f_(s), LN2, em_c + m);
        alpha = mk_c ? na : alpha;
        m_cur = mx;
    }

    // log_Z = logsumexp(alpha + end_transitions)  (computed identically by both warps)
    float logZ;
    {
        float v = alpha + endt[lane];
        float mz = v;
#pragma unroll
        for (int off = 16; off; off >>= 1)
            mz = fmaxf(mz, __shfl_xor_sync(FULL, mz, off));
        float ez = ex2f_((v - mz) * L2E);
#pragma unroll
        for (int off = 16; off; off >>= 1)
            ez += __shfl_xor_sync(FULL, ez, off);
        logZ = fmaf(lg2f_(ez), LN2, mz);
    }

    // ---- gold-path score: each warp covers its half of the T range ----
    float sc = 0.f; int cnt = 0;
    const int tbeg = half * (T_ / 2);
#pragma unroll 2
    for (int base = tbeg; base < tbeg + T_ / 2; base += 32) {
        const int t = base + lane;
        const int m_t = mk[t * B_ + b];
        cnt += m_t;
        if (m_t) {
            const int tg = tags[t * B_ + b];
            sc += em[((size_t)t * B_ + b) * M_ + tg];
            if (t > 0) {
                const int mp = mk[(t - 1) * B_ + b];
                const int tgp = mp ? tags[(t - 1) * B_ + b] : 1;
                sc += trans[tgp * M_ + tg] * rcpf_(wt[(t - 1) * B_ + b]);
            }
        }
    }
#pragma unroll
    for (int off = 16; off; off >>= 1) {
        sc  += __shfl_xor_sync(FULL, sc, off);
        cnt += __shfl_xor_sync(FULL, cnt, off);
    }
    if (lane == 0) { s_sc[pair][half] = sc; s_cnt[pair][half] = cnt; }
    __syncthreads();
    if (half == 0 && lane == 0) {
        float st = s_sc[pair][0] + s_sc[pair][1];
        const int cn = s_cnt[pair][0] + s_cnt[pair][1];
        st += startt[tags[b]] + endt[tags[(size_t)(cn - 1) * B_ + b]];
        g_nllh[b] = logZ - st;
    }

    // ---- last-block folds the deterministic final reduction ----
    __threadfence();
    __syncthreads();
    if (threadIdx.x == 0)
        s_last = (atomicAdd(&g_done, 1) == (int)gridDim.x - 1) ? 1 : 0;
    __syncthreads();
    if (s_last && warp == 0) {
        float v = 0.f;
#pragma unroll
        for (int k = 0; k < B_ / 32; ++k) {
            float x;
            asm volatile("ld.global.cg.f32 %0, [%1];" : "=f"(x) : "l"(g_nllh + k * 32 + lane));
            v += x;
        }
#pragma unroll
        for (int off = 16; off; off >>= 1)
            v += __shfl_xor_sync(FULL, v, off);
        if (lane == 0) { out[0] = v; g_done = 0; }
    }
}

extern "C" void kernel_launch(void* const* d_in, const int* in_sizes, int n_in,
                              void* d_out, int out_size)
{
    const float* em     = (const float*)d_in[0];
    const int*   tags   = (const int*)  d_in[1];
    const float* wt     = (const float*)d_in[2];
    const int*   mask   = (const int*)  d_in[3];
    const float* trans  = (const float*)d_in[4];
    const float* startt = (const float*)d_in[5];
    const float* endt   = (const float*)d_in[6];

    crf_kernel<<<B_ / 2, 128>>>(em, tags, wt, mask, trans, startt, endt, (float*)d_out);
}